// round 2
// baseline (speedup 1.0000x reference)
#include <cuda_runtime.h>
#include <cuda_bf16.h>
#include <cstdint>

// Problem constants
#define BB 4
#define SS 8192
#define DD 512
#define DFF 2048
#define KSEL 1024          // int(0.125 * 8192)
#define NTOK (BB * SS)     // 32768
#define CAP (BB * KSEL)    // 4096

// ---------------- scratch (device globals; no runtime allocation) ----------
__device__ float          g_weights[NTOK];
__device__ float          g_thresh[BB];
__device__ int            g_counts[BB];
__device__ int            g_idx[CAP];
__device__ __nv_bfloat16  g_xsel[CAP * DD];     // 4 MB
__device__ __nv_bfloat16  g_h[CAP * DFF];       // 16 MB
__device__ __nv_bfloat16  g_w1[DD * DFF];       // 2 MB
__device__ __nv_bfloat16  g_w2[DFF * DD];       // 2 MB

// ---------------- helpers ---------------------------------------------------
__device__ __forceinline__ float gelu_f(float v) {
    const float c0 = 0.7978845608028654f;   // sqrt(2/pi)
    float v3 = v * v * v;
    return 0.5f * v * (1.0f + tanhf(c0 * (v + 0.044715f * v3)));
}

__device__ __forceinline__ void ldsm_x4(uint32_t* r, uint32_t addr) {
    asm volatile("ldmatrix.sync.aligned.m8n8.x4.shared.b16 {%0,%1,%2,%3}, [%4];"
                 : "=r"(r[0]), "=r"(r[1]), "=r"(r[2]), "=r"(r[3]) : "r"(addr));
}
__device__ __forceinline__ void ldsm_x4_t(uint32_t* r, uint32_t addr) {
    asm volatile("ldmatrix.sync.aligned.m8n8.x4.trans.shared.b16 {%0,%1,%2,%3}, [%4];"
                 : "=r"(r[0]), "=r"(r[1]), "=r"(r[2]), "=r"(r[3]) : "r"(addr));
}
__device__ __forceinline__ void mma16816(float* c, const uint32_t* a, const uint32_t* b) {
    asm volatile("mma.sync.aligned.m16n8k16.row.col.f32.bf16.bf16.f32 "
                 "{%0,%1,%2,%3}, {%4,%5,%6,%7}, {%8,%9}, {%0,%1,%2,%3};"
                 : "+f"(c[0]), "+f"(c[1]), "+f"(c[2]), "+f"(c[3])
                 : "r"(a[0]), "r"(a[1]), "r"(a[2]), "r"(a[3]),
                   "r"(b[0]), "r"(b[1]));
}

// ---------------- 1. convert W1/W2 to bf16 ----------------------------------
__global__ void convert_w_kernel(const float* __restrict__ W1,
                                 const float* __restrict__ W2) {
    int i = blockIdx.x * blockDim.x + threadIdx.x;   // 0 .. 524287 (float4 units)
    const int n1 = (DD * DFF) / 4;                   // 262144
    float4 v;
    __nv_bfloat16* dst;
    if (i < n1) { v = ((const float4*)W1)[i]; dst = g_w1 + (size_t)i * 4; }
    else        { int j = i - n1; v = ((const float4*)W2)[j]; dst = g_w2 + (size_t)j * 4; }
    *(__nv_bfloat162*)(dst)     = __floats2bfloat162_rn(v.x, v.y);
    *(__nv_bfloat162*)(dst + 2) = __floats2bfloat162_rn(v.z, v.w);
}

// ---------------- 2. router weights: w[b,s] = x . Wr + br -------------------
__global__ void weights_kernel(const float* __restrict__ x,
                               const float* __restrict__ Wr,
                               const float* __restrict__ br) {
    int row  = blockIdx.x * 8 + (threadIdx.x >> 5);
    int lane = threadIdx.x & 31;
    const float4* xr  = (const float4*)(x + (size_t)row * DD);
    const float4* wr4 = (const float4*)Wr;
    float acc = 0.f;
#pragma unroll
    for (int i = 0; i < 4; ++i) {
        float4 a = xr[lane + 32 * i];
        float4 b = wr4[lane + 32 * i];
        acc += a.x * b.x + a.y * b.y + a.z * b.z + a.w * b.w;
    }
#pragma unroll
    for (int o = 16; o; o >>= 1) acc += __shfl_xor_sync(0xFFFFFFFFu, acc, o);
    if (lane == 0) g_weights[row] = acc + br[0];
}

// ---------------- 3. per-batch exact k-th largest (binary search on keys) ---
__global__ void threshold_kernel() {
    __shared__ uint32_t keys[SS];
    __shared__ int      warpsum[8];
    __shared__ uint32_t bcast;
    int b = blockIdx.x, tid = threadIdx.x;
    for (int i = tid; i < SS; i += 256) {
        uint32_t u = __float_as_uint(g_weights[b * SS + i]);
        keys[i] = (u & 0x80000000u) ? ~u : (u | 0x80000000u);
    }
    __syncthreads();
    uint32_t lo = 0u, hi = 0xFFFFFFFFu;
    for (int it = 0; it < 32 && lo < hi; ++it) {
        uint32_t mid = (uint32_t)(((unsigned long long)lo + hi + 1ull) >> 1);
        int c = 0;
        for (int i = tid; i < SS; i += 256) c += (keys[i] >= mid);
#pragma unroll
        for (int o = 16; o; o >>= 1) c += __shfl_xor_sync(0xFFFFFFFFu, c, o);
        if ((tid & 31) == 0) warpsum[tid >> 5] = c;
        __syncthreads();
        if (tid == 0) {
            int tot = 0;
#pragma unroll
            for (int w = 0; w < 8; ++w) tot += warpsum[w];
            bcast = (tot >= KSEL) ? 1u : 0u;
        }
        __syncthreads();
        if (bcast) lo = mid; else hi = mid - 1u;
        __syncthreads();
    }
    if (tid == 0) {
        uint32_t u = (lo & 0x80000000u) ? (lo ^ 0x80000000u) : ~lo;
        g_thresh[b] = __uint_as_float(u);
        g_counts[b] = 0;
    }
}

// ---------------- 4. compact selected token indices -------------------------
__global__ void compact_kernel() {
    int i = blockIdx.x * blockDim.x + threadIdx.x;     // 0..NTOK-1
    int b = i >> 13;                                    // /8192
    float w = g_weights[i];
    if (w > g_thresh[b]) {
        int p = atomicAdd(&g_counts[b], 1);
        g_idx[(b << 10) + p] = i;
    }
}

// ---------------- 5. gather selected rows, fp32 -> bf16 ---------------------
__global__ void gather_kernel(const float* __restrict__ x) {
    int r = blockIdx.x;                 // 0..CAP-1
    int b = r >> 10, j = r & 1023;
    bool active = j < g_counts[b];
    int tok = active ? g_idx[r] : 0;
    const float4* src = (const float4*)(x + (size_t)tok * DD);
    __nv_bfloat162* dst = (__nv_bfloat162*)(g_xsel + (size_t)r * DD);
    int c = threadIdx.x;                // 128 threads, 128 float4 per row
    float4 v = active ? src[c] : make_float4(0.f, 0.f, 0.f, 0.f);
    dst[2 * c]     = __floats2bfloat162_rn(v.x, v.y);
    dst[2 * c + 1] = __floats2bfloat162_rn(v.z, v.w);
}

// ---------------- 6/7. bf16 tensor-core GEMM --------------------------------
// PHASE 1: H = gelu(Xsel @ W1 + b1)         [CAP,512]x[512,2048] -> bf16 g_h
// PHASE 2: out[tok] = (H @ W2 + b2) * w     [CAP,2048]x[2048,512] -> scatter
template<int PHASE>
__global__ void __launch_bounds__(256) gemm_kernel(const float* __restrict__ bias,
                                                   float* __restrict__ outp) {
    constexpr int N  = (PHASE == 1) ? DFF : DD;
    constexpr int K  = (PHASE == 1) ? DD  : DFF;
    constexpr int BM = 128;
    constexpr int BN = (PHASE == 1) ? 128 : 64;
    constexpr int BK = 32;
    constexpr int NT = BN / 16;                 // n-tiles of 8 per warp

    const __nv_bfloat16* __restrict__ A  = (PHASE == 1) ? g_xsel : g_h;
    const __nv_bfloat16* __restrict__ Bm = (PHASE == 1) ? g_w1   : g_w2;

    __shared__ __align__(16) __nv_bfloat16 sA[BM][BK + 16];   // stride 96 B
    __shared__ __align__(16) __nv_bfloat16 sB[BK][BN + 16];   // stride 288/160 B

    int tid  = threadIdx.x;
    int warp = tid >> 5, lane = tid & 31;
    int wm = warp & 3;          // 4 warps along M, 32 rows each
    int wn = warp >> 2;         // 2 warps along N, BN/2 cols each
    int bm0 = blockIdx.y * BM;
    int bn0 = blockIdx.x * BN;

    float acc[2][NT][4];
#pragma unroll
    for (int m = 0; m < 2; ++m)
#pragma unroll
        for (int n = 0; n < NT; ++n)
#pragma unroll
            for (int q = 0; q < 4; ++q) acc[m][n][q] = 0.f;

    for (int k0 = 0; k0 < K; k0 += BK) {
        // load A tile: 128x32 bf16 = 1024 uint2
#pragma unroll
        for (int i = 0; i < 4; ++i) {
            int lin = tid + 256 * i;
            int r = lin >> 3, c = (lin & 7) * 4;
            *(uint2*)&sA[r][c] = *(const uint2*)&A[(size_t)(bm0 + r) * K + k0 + c];
        }
        // load B tile: 32xBN bf16 = BN*8 uint2
#pragma unroll
        for (int i = 0; i < BN / 32; ++i) {
            int lin = tid + 256 * i;
            int r = lin / (BN / 4), c = (lin % (BN / 4)) * 4;
            *(uint2*)&sB[r][c] = *(const uint2*)&Bm[(size_t)(k0 + r) * N + bn0 + c];
        }
        __syncthreads();
#pragma unroll
        for (int ks = 0; ks < BK; ks += 16) {
            uint32_t af[2][4];
#pragma unroll
            for (int mt = 0; mt < 2; ++mt) {
                int row = wm * 32 + mt * 16 + (lane & 15);
                int col = ks + ((lane >> 4) << 3);
                uint32_t addr = (uint32_t)__cvta_generic_to_shared(&sA[row][col]);
                ldsm_x4(af[mt], addr);
            }
            uint32_t bfr[NT][2];
#pragma unroll
            for (int np = 0; np < NT / 2; ++np) {
                int krow = ks + (lane & 15);
                int col  = wn * (BN / 2) + np * 16 + ((lane >> 4) << 3);
                uint32_t addr = (uint32_t)__cvta_generic_to_shared(&sB[krow][col]);
                uint32_t tmp[4];
                ldsm_x4_t(tmp, addr);
                bfr[2 * np][0]     = tmp[0];
                bfr[2 * np][1]     = tmp[1];
                bfr[2 * np + 1][0] = tmp[2];
                bfr[2 * np + 1][1] = tmp[3];
            }
#pragma unroll
            for (int mt = 0; mt < 2; ++mt)
#pragma unroll
                for (int nt = 0; nt < NT; ++nt)
                    mma16816(acc[mt][nt], af[mt], bfr[nt]);
        }
        __syncthreads();
    }

    // epilogue
#pragma unroll
    for (int mt = 0; mt < 2; ++mt) {
        int r0 = bm0 + wm * 32 + mt * 16 + (lane >> 2);
        int r1 = r0 + 8;
        if constexpr (PHASE == 1) {
#pragma unroll
            for (int nt = 0; nt < NT; ++nt) {
                int gc = bn0 + wn * (BN / 2) + nt * 8 + (lane & 3) * 2;
                float bb0 = bias[gc], bb1 = bias[gc + 1];
                float v00 = gelu_f(acc[mt][nt][0] + bb0);
                float v01 = gelu_f(acc[mt][nt][1] + bb1);
                float v10 = gelu_f(acc[mt][nt][2] + bb0);
                float v11 = gelu_f(acc[mt][nt][3] + bb1);
                *(__nv_bfloat162*)&g_h[(size_t)r0 * DFF + gc] = __floats2bfloat162_rn(v00, v01);
                *(__nv_bfloat162*)&g_h[(size_t)r1 * DFF + gc] = __floats2bfloat162_rn(v10, v11);
            }
        } else {
            int  bi0 = r0 >> 10; bool act0 = (r0 & 1023) < g_counts[bi0];
            int  bi1 = r1 >> 10; bool act1 = (r1 & 1023) < g_counts[bi1];
            int  tok0 = act0 ? g_idx[r0] : 0;
            int  tok1 = act1 ? g_idx[r1] : 0;
            float w0 = act0 ? g_weights[tok0] : 0.f;
            float w1 = act1 ? g_weights[tok1] : 0.f;
#pragma unroll
            for (int nt = 0; nt < NT; ++nt) {
                int gc = bn0 + wn * (BN / 2) + nt * 8 + (lane & 3) * 2;
                float bb0 = bias[gc], bb1 = bias[gc + 1];
                if (act0) {
                    float2 v = make_float2((acc[mt][nt][0] + bb0) * w0,
                                           (acc[mt][nt][1] + bb1) * w0);
                    *(float2*)&outp[(size_t)tok0 * DD + gc] = v;
                }
                if (act1) {
                    float2 v = make_float2((acc[mt][nt][2] + bb0) * w1,
                                           (acc[mt][nt][3] + bb1) * w1);
                    *(float2*)&outp[(size_t)tok1 * DD + gc] = v;
                }
            }
        }
    }
}

// ---------------- launch -----------------------------------------------------
extern "C" void kernel_launch(void* const* d_in, const int* in_sizes, int n_in,
                              void* d_out, int out_size) {
    const float* x  = (const float*)d_in[0];
    // d_in[1] = position_ids (unused by the reference math)
    const float* Wr = (const float*)d_in[2];
    const float* br = (const float*)d_in[3];
    const float* W1 = (const float*)d_in[4];
    const float* b1 = (const float*)d_in[5];
    const float* W2 = (const float*)d_in[6];
    const float* b2 = (const float*)d_in[7];
    float* out = (float*)d_out;

    // passthrough baseline: out = x
    cudaMemcpyAsync(out, x, (size_t)NTOK * DD * sizeof(float),
                    cudaMemcpyDeviceToDevice, 0);

    convert_w_kernel<<<2048, 256>>>(W1, W2);
    weights_kernel<<<NTOK / 8, 256>>>(x, Wr, br);
    threshold_kernel<<<BB, 256>>>();
    compact_kernel<<<NTOK / 256, 256>>>();
    gather_kernel<<<CAP, 128>>>(x);
    gemm_kernel<1><<<dim3(DFF / 128, CAP / 128), 256>>>(b1, nullptr);
    gemm_kernel<2><<<dim3(DD / 64,  CAP / 128), 256>>>(b2, out);
}

// round 3
// speedup vs baseline: 1.1335x; 1.1335x over previous
#include <cuda_runtime.h>
#include <cuda_bf16.h>
#include <cstdint>

// Problem constants
#define BB 4
#define SS 8192
#define DD 512
#define DFF 2048
#define KSEL 1024          // int(0.125 * 8192)
#define NTOK (BB * SS)     // 32768
#define CAP (BB * KSEL)    // 4096

// ---------------- scratch (device globals; no runtime allocation) ----------
__device__ float          g_weights[NTOK];
__device__ int            g_counts[BB];
__device__ int            g_idx[CAP];
__device__ __nv_bfloat16  g_xsel[CAP * DD];     // 4 MB
__device__ __nv_bfloat16  g_h[CAP * DFF];       // 16 MB
__device__ __nv_bfloat16  g_w1[DD * DFF];       // 2 MB
__device__ __nv_bfloat16  g_w2[DFF * DD];       // 2 MB

// ---------------- helpers ---------------------------------------------------
__device__ __forceinline__ float gelu_f(float v) {
    const float c0 = 0.7978845608028654f;   // sqrt(2/pi)
    float v3 = v * v * v;
    return 0.5f * v * (1.0f + tanhf(c0 * (v + 0.044715f * v3)));
}

__device__ __forceinline__ void ldsm_x4(uint32_t* r, uint32_t addr) {
    asm volatile("ldmatrix.sync.aligned.m8n8.x4.shared.b16 {%0,%1,%2,%3}, [%4];"
                 : "=r"(r[0]), "=r"(r[1]), "=r"(r[2]), "=r"(r[3]) : "r"(addr));
}
__device__ __forceinline__ void ldsm_x4_t(uint32_t* r, uint32_t addr) {
    asm volatile("ldmatrix.sync.aligned.m8n8.x4.trans.shared.b16 {%0,%1,%2,%3}, [%4];"
                 : "=r"(r[0]), "=r"(r[1]), "=r"(r[2]), "=r"(r[3]) : "r"(addr));
}
__device__ __forceinline__ void mma16816(float* c, const uint32_t* a, const uint32_t* b) {
    asm volatile("mma.sync.aligned.m16n8k16.row.col.f32.bf16.bf16.f32 "
                 "{%0,%1,%2,%3}, {%4,%5,%6,%7}, {%8,%9}, {%0,%1,%2,%3};"
                 : "+f"(c[0]), "+f"(c[1]), "+f"(c[2]), "+f"(c[3])
                 : "r"(a[0]), "r"(a[1]), "r"(a[2]), "r"(a[3]),
                   "r"(b[0]), "r"(b[1]));
}
__device__ __forceinline__ void cp_async16(uint32_t dst, const void* src) {
    asm volatile("cp.async.cg.shared.global [%0], [%1], 16;\n" :: "r"(dst), "l"(src));
}

// ---------------- 1. fused out=x copy + router weights ----------------------
__global__ void __launch_bounds__(256) copyw_kernel(const float* __restrict__ x,
                                                    const float* __restrict__ Wr,
                                                    const float* __restrict__ br,
                                                    float* __restrict__ out) {
    int row  = blockIdx.x * 8 + (threadIdx.x >> 5);
    int lane = threadIdx.x & 31;
    const float4* xr  = (const float4*)(x + (size_t)row * DD);
    float4*       orw = (float4*)(out + (size_t)row * DD);
    const float4* wr4 = (const float4*)Wr;
    float acc = 0.f;
#pragma unroll
    for (int i = 0; i < 4; ++i) {
        float4 a = xr[lane + 32 * i];
        float4 w = wr4[lane + 32 * i];
        orw[lane + 32 * i] = a;
        acc += a.x * w.x + a.y * w.y + a.z * w.z + a.w * w.w;
    }
#pragma unroll
    for (int o = 16; o; o >>= 1) acc += __shfl_xor_sync(0xFFFFFFFFu, acc, o);
    if (lane == 0) g_weights[row] = acc + br[0];
}

// ---------------- 2. convert W1/W2 to bf16 ----------------------------------
__global__ void convert_w_kernel(const float* __restrict__ W1,
                                 const float* __restrict__ W2) {
    int i = blockIdx.x * blockDim.x + threadIdx.x;   // float4 units
    const int n1 = (DD * DFF) / 4;
    float4 v;
    __nv_bfloat16* dst;
    if (i < n1) { v = ((const float4*)W1)[i]; dst = g_w1 + (size_t)i * 4; }
    else        { int j = i - n1; v = ((const float4*)W2)[j]; dst = g_w2 + (size_t)j * 4; }
    *(__nv_bfloat162*)(dst)     = __floats2bfloat162_rn(v.x, v.y);
    *(__nv_bfloat162*)(dst + 2) = __floats2bfloat162_rn(v.z, v.w);
}

// ---------------- 3. radix-select k-th largest + fused compaction -----------
__global__ void __launch_bounds__(256) select_kernel() {
    __shared__ uint32_t keys[SS];
    __shared__ int hist[256];
    __shared__ int cum[256];
    __shared__ int s_sel, s_kk, s_cnt;
    int b = blockIdx.x, tid = threadIdx.x, lane = tid & 31;

    for (int i = tid; i < SS; i += 256) {
        uint32_t u = __float_as_uint(g_weights[b * SS + i]);
        keys[i] = (u & 0x80000000u) ? ~u : (u | 0x80000000u);
    }
    if (tid == 0) { s_kk = KSEL; s_cnt = 0; }
    __syncthreads();

    uint32_t pref = 0, msk = 0;
#pragma unroll
    for (int shift = 24; shift >= 0; shift -= 8) {
        hist[tid] = 0;
        __syncthreads();
        for (int i = tid; i < SS; i += 256) {
            uint32_t u = keys[i];
            int d = ((u & msk) == pref) ? (int)((u >> shift) & 255u) : 256;
            unsigned grp = __match_any_sync(0xFFFFFFFFu, d);
            if ((int)(__ffs(grp) - 1) == lane && d < 256)
                atomicAdd(&hist[d], __popc(grp));
        }
        __syncthreads();
        cum[tid] = hist[tid];
        __syncthreads();
#pragma unroll
        for (int off = 1; off < 256; off <<= 1) {
            int v = (tid + off < 256) ? cum[tid + off] : 0;
            __syncthreads();
            cum[tid] += v;
            __syncthreads();
        }
        int kk = s_kk;
        int h  = hist[tid];
        int c  = cum[tid];
        int cn = (tid < 255) ? cum[tid + 1] : 0;
        __syncthreads();
        if (c >= kk && (tid == 255 || cn < kk)) {
            s_sel = tid;
            s_kk  = kk - (c - h);
        }
        __syncthreads();
        pref |= ((uint32_t)s_sel) << shift;
        msk  |= 255u << shift;
        __syncthreads();
    }
    // pref == key of the KSEL-th largest element; strict-> compare matches jax
    for (int i = tid; i < SS; i += 256) {
        if (keys[i] > pref) {
            int p = atomicAdd(&s_cnt, 1);
            g_idx[(b << 10) + p] = b * SS + i;
        }
    }
    __syncthreads();
    if (tid == 0) g_counts[b] = s_cnt;
}

// ---------------- 4. gather selected rows, fp32 -> bf16 ---------------------
__global__ void gather_kernel(const float* __restrict__ x) {
    int r = blockIdx.x;                 // 0..CAP-1
    int b = r >> 10, j = r & 1023;
    bool active = j < g_counts[b];
    int tok = active ? g_idx[r] : 0;
    const float4* src = (const float4*)(x + (size_t)tok * DD);
    __nv_bfloat162* dst = (__nv_bfloat162*)(g_xsel + (size_t)r * DD);
    int c = threadIdx.x;                // 128 threads, 128 float4 per row
    float4 v = active ? src[c] : make_float4(0.f, 0.f, 0.f, 0.f);
    dst[2 * c]     = __floats2bfloat162_rn(v.x, v.y);
    dst[2 * c + 1] = __floats2bfloat162_rn(v.z, v.w);
}

// ---------------- 5/6. pipelined bf16 tensor-core GEMM ----------------------
// PHASE 1: H = gelu(Xsel @ W1 + b1)         [CAP,512]x[512,2048] -> bf16 g_h
// PHASE 2: out[tok] = (H @ W2 + b2) * w     [CAP,2048]x[2048,512] -> scatter
template<int PHASE>
__global__ void __launch_bounds__(256) gemm_kernel(const float* __restrict__ bias,
                                                   float* __restrict__ outp) {
    constexpr int N      = (PHASE == 1) ? DFF : DD;
    constexpr int K      = (PHASE == 1) ? DD  : DFF;
    constexpr int BM     = 128;
    constexpr int BN     = (PHASE == 1) ? 128 : 64;
    constexpr int BK     = 64;
    constexpr int STAGES = 3;
    constexpr int KT     = K / BK;
    constexpr int NT     = BN / 16;            // n8-tiles per warp
    constexpr int BCH    = BN / 8;             // 16B chunks per B row

    extern __shared__ __align__(16) char smem[];
    char* sAb = smem;                          // STAGES * BM*BK*2
    char* sBb = smem + (size_t)STAGES * BM * BK * 2;

    const __nv_bfloat16* __restrict__ A  = (PHASE == 1) ? g_xsel : g_h;
    const __nv_bfloat16* __restrict__ Bm = (PHASE == 1) ? g_w1   : g_w2;

    int tid = threadIdx.x, warp = tid >> 5, lane = tid & 31;
    int wm = warp & 3;                          // 4 warps along M (32 rows each)
    int wn = warp >> 2;                         // 2 warps along N (BN/2 cols each)
    int bm0 = blockIdx.y * BM;
    int bn0 = blockIdx.x * BN;

    float acc[2][NT][4] = {};

    auto load_stage = [&](int k0, int s) {
        char* a = sAb + (size_t)s * BM * BK * 2;
        char* b = sBb + (size_t)s * BK * BN * 2;
#pragma unroll
        for (int i = 0; i < (BM * 8) / 256; ++i) {       // A: 1024 chunks of 16B
            int lin = tid + 256 * i;
            int r = lin >> 3, c = lin & 7;
            uint32_t dst = (uint32_t)__cvta_generic_to_shared(
                a + ((size_t)((r << 3) + (c ^ (r & 7))) << 4));
            cp_async16(dst, &A[(size_t)(bm0 + r) * K + k0 + c * 8]);
        }
#pragma unroll
        for (int i = 0; i < (BK * BCH) / 256; ++i) {     // B chunks
            int lin = tid + 256 * i;
            int r = lin / BCH, c = lin % BCH;
            uint32_t dst = (uint32_t)__cvta_generic_to_shared(
                b + ((size_t)(r * BCH + (c ^ (r & 7))) << 4));
            cp_async16(dst, &Bm[(size_t)(k0 + r) * N + bn0 + c * 8]);
        }
    };

#pragma unroll
    for (int s = 0; s < STAGES - 1; ++s) {
        load_stage(s * BK, s);
        asm volatile("cp.async.commit_group;\n");
    }

    for (int kt = 0; kt < KT; ++kt) {
        asm volatile("cp.async.wait_group %0;\n" :: "n"(STAGES - 2));
        __syncthreads();
        int kload = kt + STAGES - 1;
        if (kload < KT) load_stage(kload * BK, kload % STAGES);
        asm volatile("cp.async.commit_group;\n");

        int s = kt % STAGES;
        char* a = sAb + (size_t)s * BM * BK * 2;
        char* b = sBb + (size_t)s * BK * BN * 2;
#pragma unroll
        for (int ks = 0; ks < BK; ks += 16) {
            uint32_t af[2][4];
#pragma unroll
            for (int mt = 0; mt < 2; ++mt) {
                int row = wm * 32 + mt * 16 + (lane & 15);
                int ch  = (ks >> 3) + (lane >> 4);
                uint32_t addr = (uint32_t)__cvta_generic_to_shared(
                    a + ((size_t)((row << 3) + (ch ^ (row & 7))) << 4));
                ldsm_x4(af[mt], addr);
            }
            uint32_t bfr[NT][2];
#pragma unroll
            for (int np = 0; np < NT / 2; ++np) {
                int krow = ks + (lane & 15);
                int col  = wn * (BN / 2) + np * 16 + ((lane >> 4) << 3);
                int ch   = col >> 3;
                uint32_t addr = (uint32_t)__cvta_generic_to_shared(
                    b + ((size_t)(krow * BCH + (ch ^ (krow & 7))) << 4));
                uint32_t t[4];
                ldsm_x4_t(t, addr);
                bfr[2 * np][0]     = t[0];
                bfr[2 * np][1]     = t[1];
                bfr[2 * np + 1][0] = t[2];
                bfr[2 * np + 1][1] = t[3];
            }
#pragma unroll
            for (int mt = 0; mt < 2; ++mt)
#pragma unroll
                for (int nt = 0; nt < NT; ++nt)
                    mma16816(acc[mt][nt], af[mt], bfr[nt]);
        }
    }

    // epilogue
#pragma unroll
    for (int mt = 0; mt < 2; ++mt) {
        int r0 = bm0 + wm * 32 + mt * 16 + (lane >> 2);
        int r1 = r0 + 8;
        if constexpr (PHASE == 1) {
#pragma unroll
            for (int nt = 0; nt < NT; ++nt) {
                int gc = bn0 + wn * (BN / 2) + nt * 8 + (lane & 3) * 2;
                float bb0 = bias[gc], bb1 = bias[gc + 1];
                float v00 = gelu_f(acc[mt][nt][0] + bb0);
                float v01 = gelu_f(acc[mt][nt][1] + bb1);
                float v10 = gelu_f(acc[mt][nt][2] + bb0);
                float v11 = gelu_f(acc[mt][nt][3] + bb1);
                *(__nv_bfloat162*)&g_h[(size_t)r0 * DFF + gc] = __floats2bfloat162_rn(v00, v01);
                *(__nv_bfloat162*)&g_h[(size_t)r1 * DFF + gc] = __floats2bfloat162_rn(v10, v11);
            }
        } else {
            int  bi0 = r0 >> 10; bool act0 = (r0 & 1023) < g_counts[bi0];
            int  bi1 = r1 >> 10; bool act1 = (r1 & 1023) < g_counts[bi1];
            int  tok0 = act0 ? g_idx[r0] : 0;
            int  tok1 = act1 ? g_idx[r1] : 0;
            float w0 = act0 ? g_weights[tok0] : 0.f;
            float w1 = act1 ? g_weights[tok1] : 0.f;
#pragma unroll
            for (int nt = 0; nt < NT; ++nt) {
                int gc = bn0 + wn * (BN / 2) + nt * 8 + (lane & 3) * 2;
                float bb0 = bias[gc], bb1 = bias[gc + 1];
                if (act0) {
                    float2 v = make_float2((acc[mt][nt][0] + bb0) * w0,
                                           (acc[mt][nt][1] + bb1) * w0);
                    *(float2*)&outp[(size_t)tok0 * DD + gc] = v;
                }
                if (act1) {
                    float2 v = make_float2((acc[mt][nt][2] + bb0) * w1,
                                           (acc[mt][nt][3] + bb1) * w1);
                    *(float2*)&outp[(size_t)tok1 * DD + gc] = v;
                }
            }
        }
    }
}

// ---------------- launch -----------------------------------------------------
extern "C" void kernel_launch(void* const* d_in, const int* in_sizes, int n_in,
                              void* d_out, int out_size) {
    const float* x  = (const float*)d_in[0];
    // d_in[1] = position_ids (unused by the reference math)
    const float* Wr = (const float*)d_in[2];
    const float* br = (const float*)d_in[3];
    const float* W1 = (const float*)d_in[4];
    const float* b1 = (const float*)d_in[5];
    const float* W2 = (const float*)d_in[6];
    const float* b2 = (const float*)d_in[7];
    float* out = (float*)d_out;

    constexpr int SMEM1 = 3 * (128 * 64 + 64 * 128) * 2;  // 96 KB
    constexpr int SMEM2 = 3 * (128 * 64 + 64 * 64) * 2;   // 72 KB
    cudaFuncSetAttribute(gemm_kernel<1>, cudaFuncAttributeMaxDynamicSharedMemorySize, SMEM1);
    cudaFuncSetAttribute(gemm_kernel<2>, cudaFuncAttributeMaxDynamicSharedMemorySize, SMEM2);

    copyw_kernel<<<NTOK / 8, 256>>>(x, Wr, br, out);
    convert_w_kernel<<<2048, 256>>>(W1, W2);
    select_kernel<<<BB, 256>>>();
    gather_kernel<<<CAP, 128>>>(x);
    gemm_kernel<1><<<dim3(DFF / 128, CAP / 128), 256, SMEM1>>>(b1, nullptr);
    gemm_kernel<2><<<dim3(DD / 64,  CAP / 128), 256, SMEM2>>>(b2, out);
}

// round 7
// speedup vs baseline: 1.7443x; 1.5389x over previous
#include <cuda_runtime.h>
#include <cuda_bf16.h>
#include <cstdint>

// Problem constants
#define BB 4
#define SS 8192
#define DD 512
#define DFF 2048
#define KSEL 1024          // int(0.125 * 8192)
#define NTOK (BB * SS)     // 32768
#define CAP (BB * KSEL)    // 4096

// ---------------- scratch (device globals; no runtime allocation) ----------
__device__ float          g_weights[NTOK];
__device__ int            g_counts[BB];
__device__ int            g_idx[CAP];
__device__ __nv_bfloat16  g_xsel[CAP * DD];     // 4 MB
__device__ __nv_bfloat16  g_h[CAP * DFF];       // 16 MB
__device__ __nv_bfloat16  g_w1[DD * DFF];       // 2 MB   [512, 2048] row-major
__device__ __nv_bfloat16  g_w2[DFF * DD];       // 2 MB   [2048, 512] row-major

// ---------------- helpers ---------------------------------------------------
__device__ __forceinline__ float gelu_f(float v) {
    const float c0 = 0.7978845608028654f;   // sqrt(2/pi)
    float v3 = v * v * v;
    return 0.5f * v * (1.0f + tanhf(c0 * (v + 0.044715f * v3)));
}

__device__ __forceinline__ void ldsm_x4(uint32_t* r, uint32_t addr) {
    asm volatile("ldmatrix.sync.aligned.m8n8.x4.shared.b16 {%0,%1,%2,%3}, [%4];"
                 : "=r"(r[0]), "=r"(r[1]), "=r"(r[2]), "=r"(r[3]) : "r"(addr));
}
__device__ __forceinline__ void ldsm_x4_t(uint32_t* r, uint32_t addr) {
    asm volatile("ldmatrix.sync.aligned.m8n8.x4.trans.shared.b16 {%0,%1,%2,%3}, [%4];"
                 : "=r"(r[0]), "=r"(r[1]), "=r"(r[2]), "=r"(r[3]) : "r"(addr));
}
__device__ __forceinline__ void mma16816(float* c, const uint32_t* a, const uint32_t* b) {
    asm volatile("mma.sync.aligned.m16n8k16.row.col.f32.bf16.bf16.f32 "
                 "{%0,%1,%2,%3}, {%4,%5,%6,%7}, {%8,%9}, {%0,%1,%2,%3};"
                 : "+f"(c[0]), "+f"(c[1]), "+f"(c[2]), "+f"(c[3])
                 : "r"(a[0]), "r"(a[1]), "r"(a[2]), "r"(a[3]),
                   "r"(b[0]), "r"(b[1]));
}
__device__ __forceinline__ void cp_async16(uint32_t dst, const void* src) {
    asm volatile("cp.async.cg.shared.global [%0], [%1], 16;\n" :: "r"(dst), "l"(src));
}

// ---------------- 1. fused out=x copy + router weights ----------------------
__global__ void __launch_bounds__(256) copyw_kernel(const float* __restrict__ x,
                                                    const float* __restrict__ Wr,
                                                    const float* __restrict__ br,
                                                    float* __restrict__ out) {
    int row  = blockIdx.x * 8 + (threadIdx.x >> 5);
    int lane = threadIdx.x & 31;
    const float4* xr  = (const float4*)(x + (size_t)row * DD);
    float4*       orw = (float4*)(out + (size_t)row * DD);
    const float4* wr4 = (const float4*)Wr;
    float acc = 0.f;
#pragma unroll
    for (int i = 0; i < 4; ++i) {
        float4 a = xr[lane + 32 * i];
        float4 w = wr4[lane + 32 * i];
        orw[lane + 32 * i] = a;
        acc += a.x * w.x + a.y * w.y + a.z * w.z + a.w * w.w;
    }
#pragma unroll
    for (int o = 16; o; o >>= 1) acc += __shfl_xor_sync(0xFFFFFFFFu, acc, o);
    if (lane == 0) g_weights[row] = acc + br[0];
}

// ---------------- 2. convert W1/W2 to bf16 ----------------------------------
__global__ void convert_w_kernel(const float* __restrict__ W1,
                                 const float* __restrict__ W2) {
    int i = blockIdx.x * blockDim.x + threadIdx.x;   // float4 units
    const int n1 = (DD * DFF) / 4;
    float4 v;
    __nv_bfloat16* dst;
    if (i < n1) { v = ((const float4*)W1)[i]; dst = g_w1 + (size_t)i * 4; }
    else        { int j = i - n1; v = ((const float4*)W2)[j]; dst = g_w2 + (size_t)j * 4; }
    *(__nv_bfloat162*)(dst)     = __floats2bfloat162_rn(v.x, v.y);
    *(__nv_bfloat162*)(dst + 2) = __floats2bfloat162_rn(v.z, v.w);
}

// ---------------- 3. radix-select k-th largest + fused compaction -----------
__global__ void __launch_bounds__(1024) select_kernel() {
    __shared__ uint32_t keys[SS];
    __shared__ int hist[256];
    __shared__ int cum[256];
    __shared__ int s_sel, s_kk, s_cnt;
    int b = blockIdx.x, tid = threadIdx.x, lane = tid & 31;

    for (int i = tid; i < SS; i += 1024) {
        uint32_t u = __float_as_uint(g_weights[b * SS + i]);
        keys[i] = (u & 0x80000000u) ? ~u : (u | 0x80000000u);
    }
    if (tid == 0) { s_kk = KSEL; s_cnt = 0; }
    __syncthreads();

    uint32_t pref = 0, msk = 0;
#pragma unroll
    for (int shift = 24; shift >= 0; shift -= 8) {
        if (tid < 256) hist[tid] = 0;
        __syncthreads();
        for (int i = tid; i < SS; i += 1024) {
            uint32_t u = keys[i];
            int d = ((u & msk) == pref) ? (int)((u >> shift) & 255u) : 256;
            unsigned grp = __match_any_sync(0xFFFFFFFFu, d);
            if ((int)(__ffs(grp) - 1) == lane && d < 256)
                atomicAdd(&hist[d], __popc(grp));
        }
        __syncthreads();
        if (tid < 256) cum[tid] = hist[tid];
        __syncthreads();
#pragma unroll
        for (int off = 1; off < 256; off <<= 1) {
            int v = 0;
            if (tid < 256 && tid + off < 256) v = cum[tid + off];
            __syncthreads();
            if (tid < 256) cum[tid] += v;
            __syncthreads();
        }
        int kk = s_kk;
        if (tid < 256) {
            int h  = hist[tid];
            int c  = cum[tid];
            int cn = (tid < 255) ? cum[tid + 1] : 0;
            if (c >= kk && (tid == 255 || cn < kk)) {
                s_sel = tid;
                s_kk  = kk - (c - h);
            }
        }
        __syncthreads();
        pref |= ((uint32_t)s_sel) << shift;
        msk  |= 255u << shift;
        __syncthreads();
    }
    // pref == key of the KSEL-th largest; strict > matches jax selection
    for (int i = tid; i < SS; i += 1024) {
        if (keys[i] > pref) {
            int p = atomicAdd(&s_cnt, 1);
            g_idx[(b << 10) + p] = b * SS + i;
        }
    }
    __syncthreads();
    if (tid == 0) g_counts[b] = s_cnt;
}

// ---------------- 4. gather selected rows, fp32 -> bf16 ---------------------
__global__ void __launch_bounds__(256) gather_kernel(const float* __restrict__ x) {
    int r = blockIdx.x * 2 + (threadIdx.x >> 7);    // 0..CAP-1
    int c = threadIdx.x & 127;
    int b = r >> 10, j = r & 1023;
    bool active = j < g_counts[b];
    int tok = active ? g_idx[r] : 0;
    const float4* src = (const float4*)(x + (size_t)tok * DD);
    __nv_bfloat162* dst = (__nv_bfloat162*)(g_xsel + (size_t)r * DD);
    float4 v = active ? src[c] : make_float4(0.f, 0.f, 0.f, 0.f);
    dst[2 * c]     = __floats2bfloat162_rn(v.x, v.y);
    dst[2 * c + 1] = __floats2bfloat162_rn(v.z, v.w);
}

// ---------------- 5/6. pipelined bf16 tensor-core GEMM ----------------------
// PHASE 1: H = gelu(Xsel @ W1 + b1)         [CAP,512]x[512,2048] -> bf16 g_h
// PHASE 2: out[tok] = (H @ W2 + b2) * w     [CAP,2048]x[2048,512] -> scatter
template<int PHASE>
__global__ void __launch_bounds__(256, 2) gemm_kernel(const float* __restrict__ bias,
                                                      float* __restrict__ outp) {
    constexpr int N      = (PHASE == 1) ? DFF : DD;
    constexpr int K      = (PHASE == 1) ? DD  : DFF;
    constexpr int BM     = 128;
    constexpr int BN     = (PHASE == 1) ? 128 : 64;
    constexpr int BK     = 64;
    constexpr int STAGES = 3;
    constexpr int KT     = K / BK;
    constexpr int NT     = BN / 16;            // n8-tiles per warp
    constexpr int BCH    = BN / 8;             // 16B chunks per B row

    extern __shared__ __align__(16) char smem[];
    char* sAb = smem;                          // STAGES * BM*BK*2
    char* sBb = smem + (size_t)STAGES * BM * BK * 2;

    const __nv_bfloat16* __restrict__ A  = (PHASE == 1) ? g_xsel : g_h;
    const __nv_bfloat16* __restrict__ Bm = (PHASE == 1) ? g_w1   : g_w2;

    int tid = threadIdx.x, warp = tid >> 5, lane = tid & 31;
    int wm = warp & 3;                          // 4 warps along M (32 rows each)
    int wn = warp >> 2;                         // 2 warps along N (BN/2 cols each)
    int bm0 = blockIdx.y * BM;
    int bn0 = blockIdx.x * BN;

    float acc[2][NT][4] = {};

    auto load_stage = [&](int k0, int s) {
        char* a = sAb + (size_t)s * BM * BK * 2;
        char* b = sBb + (size_t)s * BK * BN * 2;
#pragma unroll
        for (int i = 0; i < (BM * 8) / 256; ++i) {       // A: 1024 chunks of 16B
            int lin = tid + 256 * i;
            int r = lin >> 3, c = lin & 7;
            uint32_t dst = (uint32_t)__cvta_generic_to_shared(
                a + ((size_t)((r << 3) + (c ^ (r & 7))) << 4));
            cp_async16(dst, &A[(size_t)(bm0 + r) * K + k0 + c * 8]);
        }
#pragma unroll
        for (int i = 0; i < (BK * BCH) / 256; ++i) {     // B chunks
            int lin = tid + 256 * i;
            int r = lin / BCH, c = lin % BCH;
            uint32_t dst = (uint32_t)__cvta_generic_to_shared(
                b + ((size_t)(r * BCH + (c ^ (r & 7))) << 4));
            cp_async16(dst, &Bm[(size_t)(k0 + r) * N + bn0 + c * 8]);
        }
    };

#pragma unroll
    for (int s = 0; s < STAGES - 1; ++s) {
        load_stage(s * BK, s);
        asm volatile("cp.async.commit_group;\n");
    }

    for (int kt = 0; kt < KT; ++kt) {
        asm volatile("cp.async.wait_group %0;\n" :: "n"(STAGES - 2));
        __syncthreads();
        int kload = kt + STAGES - 1;
        if (kload < KT) load_stage(kload * BK, kload % STAGES);
        asm volatile("cp.async.commit_group;\n");

        int s = kt % STAGES;
        char* a = sAb + (size_t)s * BM * BK * 2;
        char* b = sBb + (size_t)s * BK * BN * 2;
#pragma unroll
        for (int ks = 0; ks < BK; ks += 16) {
            uint32_t af[2][4];
#pragma unroll
            for (int mt = 0; mt < 2; ++mt) {
                int row = wm * 32 + mt * 16 + (lane & 15);
                int ch  = (ks >> 3) + (lane >> 4);
                uint32_t addr = (uint32_t)__cvta_generic_to_shared(
                    a + ((size_t)((row << 3) + (ch ^ (row & 7))) << 4));
                ldsm_x4(af[mt], addr);
            }
            uint32_t bfr[NT][2];
#pragma unroll
            for (int np = 0; np < NT / 2; ++np) {
                int krow = ks + (lane & 15);
                int col  = wn * (BN / 2) + np * 16 + ((lane >> 4) << 3);
                int ch   = col >> 3;
                uint32_t addr = (uint32_t)__cvta_generic_to_shared(
                    b + ((size_t)(krow * BCH + (ch ^ (krow & 7))) << 4));
                uint32_t t[4];
                ldsm_x4_t(t, addr);
                bfr[2 * np][0]     = t[0];
                bfr[2 * np][1]     = t[1];
                bfr[2 * np + 1][0] = t[2];
                bfr[2 * np + 1][1] = t[3];
            }
#pragma unroll
            for (int mt = 0; mt < 2; ++mt)
#pragma unroll
                for (int nt = 0; nt < NT; ++nt)
                    mma16816(acc[mt][nt], af[mt], bfr[nt]);
        }
    }

    // epilogue
#pragma unroll
    for (int mt = 0; mt < 2; ++mt) {
        int r0 = bm0 + wm * 32 + mt * 16 + (lane >> 2);
        int r1 = r0 + 8;
        if constexpr (PHASE == 1) {
#pragma unroll
            for (int nt = 0; nt < NT; ++nt) {
                int gc = bn0 + wn * (BN / 2) + nt * 8 + (lane & 3) * 2;
                float bb0 = bias[gc], bb1 = bias[gc + 1];
                float v00 = gelu_f(acc[mt][nt][0] + bb0);
                float v01 = gelu_f(acc[mt][nt][1] + bb1);
                float v10 = gelu_f(acc[mt][nt][2] + bb0);
                float v11 = gelu_f(acc[mt][nt][3] + bb1);
                *(__nv_bfloat162*)&g_h[(size_t)r0 * DFF + gc] = __floats2bfloat162_rn(v00, v01);
                *(__nv_bfloat162*)&g_h[(size_t)r1 * DFF + gc] = __floats2bfloat162_rn(v10, v11);
            }
        } else {
            int  bi0 = r0 >> 10; bool act0 = (r0 & 1023) < g_counts[bi0];
            int  bi1 = r1 >> 10; bool act1 = (r1 & 1023) < g_counts[bi1];
            int  tok0 = act0 ? g_idx[r0] : 0;
            int  tok1 = act1 ? g_idx[r1] : 0;
            float w0 = act0 ? g_weights[tok0] : 0.f;
            float w1 = act1 ? g_weights[tok1] : 0.f;
#pragma unroll
            for (int nt = 0; nt < NT; ++nt) {
                int gc = bn0 + wn * (BN / 2) + nt * 8 + (lane & 3) * 2;
                float bb0 = bias[gc], bb1 = bias[gc + 1];
                if (act0) {
                    float2 v = make_float2((acc[mt][nt][0] + bb0) * w0,
                                           (acc[mt][nt][1] + bb1) * w0);
                    *(float2*)&outp[(size_t)tok0 * DD + gc] = v;
                }
                if (act1) {
                    float2 v = make_float2((acc[mt][nt][2] + bb0) * w1,
                                           (acc[mt][nt][3] + bb1) * w1);
                    *(float2*)&outp[(size_t)tok1 * DD + gc] = v;
                }
            }
        }
    }
}

// ---------------- launch -----------------------------------------------------
extern "C" void kernel_launch(void* const* d_in, const int* in_sizes, int n_in,
                              void* d_out, int out_size) {
    const float* x  = (const float*)d_in[0];
    // d_in[1] = position_ids (unused by the reference math)
    const float* Wr = (const float*)d_in[2];
    const float* br = (const float*)d_in[3];
    const float* W1 = (const float*)d_in[4];
    const float* b1 = (const float*)d_in[5];
    const float* W2 = (const float*)d_in[6];
    const float* b2 = (const float*)d_in[7];
    float* out = (float*)d_out;

    constexpr int SMEM1 = 3 * (128 * 64 + 64 * 128) * 2;  // 96 KB
    constexpr int SMEM2 = 3 * (128 * 64 + 64 * 64) * 2;   // 72 KB
    cudaFuncSetAttribute(gemm_kernel<1>, cudaFuncAttributeMaxDynamicSharedMemorySize, SMEM1);
    cudaFuncSetAttribute(gemm_kernel<2>, cudaFuncAttributeMaxDynamicSharedMemorySize, SMEM2);

    copyw_kernel<<<NTOK / 8, 256>>>(x, Wr, br, out);
    convert_w_kernel<<<2048, 256>>>(W1, W2);
    select_kernel<<<BB, 1024>>>();
    gather_kernel<<<CAP / 2, 256>>>(x);
    gemm_kernel<1><<<dim3(DFF / 128, CAP / 128), 256, SMEM1>>>(b1, nullptr);
    gemm_kernel<2><<<dim3(DD / 64,  CAP / 128), 256, SMEM2>>>(b2, out);
}